// round 15
// baseline (speedup 1.0000x reference)
#include <cuda_runtime.h>
#include <cuda_fp16.h>
#include <cstdint>

// Problem constants (fixed shapes):
//   x:          [16,64,64,256] fp32  -> N_ROWS=65536 rows of D_DIM=256
//   dictionary: [256,1024]     fp32  -> D_DIM x K_CODES
// Output: q_st (16777216 fp32) followed by loss (1 fp32).
//
// CORRECTNESS-CRITICAL (validated R6/R8/R12/R13, rel_err 1.744171e-6):
//   approx screen -> per-row candidates -> EXACT fp32 reference arithmetic
//   replayed on candidates: sim = sequential fmaf chain over d=0..255;
//   t1 = fl(nf + c_k); v = fl(t1 - fl(2*sim)); first-index ties via packed
//   (bits<<32|code) atomicMin. nf/c_k are sequential fp32 square-sums in d
//   order. Do NOT alter refine-path order/roundings.
// HARNESS CONSTRAINT (proven R14): PTX target is sm_103 (no 'a') — tcgen05
// and all arch-suffix instructions DO NOT ASSEMBLE. Baseline ISA only:
// mma.sync / ldmatrix / cp.async.
// Screen: int8 mma.sync m16n8k32 (s32 accum, exact integer dot; only
// quantization noise sigma~0.005 on ranking values) -> top-12 cand/row
// (R12-validated capacity). SMEM halved vs fp16 -> 2 CTAs/SM.
#define D_DIM   256
#define K_CODES 1024
#define N_ROWS  65536
#define MTILE   128
#define THREADS 256
#define NTILES  8
#define BSTR    272          // bytes per int8 smem row (mod128=16: LDSM conflict-free)
#define NCAND   3
#define CPR     12
#define XSCALE  32.0f
#define DSCALE  2500.0f
#define INV2    (2.0f / (XSCALE * DSCALE))   // v = ck - INV2 * dot_q

// SMEM layout (bytes): 112640/CTA -> 2 CTAs/SM
#define OFF_AQ    0            // x int8, 128 x BSTR            = 34816
#define OFF_B     34816        // dict int8, 2 bufs             = 69632
#define OFF_C     104448       // c_k fp32 [1024]               = 4096
#define OFF_NF    108544       // nf fp32 [128]                 = 512
#define OFF_CAND  109056       // u16 [1536]                    = 3072
#define OFF_BEST  112128       // u64 [128]                     = 1024
#define OFF_IDX   113152       // int [128]                     = 512
#define SMEM_BYTES 113664

__device__ float   g_dictT[K_CODES * D_DIM];
__device__ int8_t  g_dictQ[K_CODES * D_DIM];
__device__ float   g_c[K_CODES];
__device__ double  g_loss;

// ---- baseline-ISA helpers only (harness cannot assemble sm_103a ops) ------
__device__ __forceinline__ uint32_t smem_u32(const void* p) {
    uint32_t a;
    asm("{ .reg .u64 t; cvta.to.shared.u64 t, %1; cvt.u32.u64 %0, t; }"
        : "=r"(a) : "l"(p));
    return a;
}
__device__ __forceinline__ void cp16(uint32_t dst, const void* src) {
    asm volatile("cp.async.cg.shared.global [%0], [%1], 16;"
                 :: "r"(dst), "l"(src) : "memory");
}
#define CP_COMMIT()  asm volatile("cp.async.commit_group;" ::: "memory")
#define CP_WAIT(n)   asm volatile("cp.async.wait_group %0;" :: "n"(n) : "memory")
__device__ __forceinline__ void ldsm4(uint32_t& r0, uint32_t& r1,
                                      uint32_t& r2, uint32_t& r3, uint32_t a) {
    asm volatile("ldmatrix.sync.aligned.m8n8.x4.shared.b16 {%0,%1,%2,%3}, [%4];"
                 : "=r"(r0), "=r"(r1), "=r"(r2), "=r"(r3) : "r"(a));
}
// int8 MMA: D(s32) += A(s8 16x32 row) * B(s8 32x8 col)
__device__ __forceinline__ void imma16832(int& c0, int& c1, int& c2, int& c3,
                                          const uint32_t a[4],
                                          uint32_t b0, uint32_t b1) {
    asm volatile(
        "mma.sync.aligned.m16n8k32.row.col.s32.s8.s8.s32 "
        "{%0,%1,%2,%3}, {%4,%5,%6,%7}, {%8,%9}, {%0,%1,%2,%3};"
        : "+r"(c0), "+r"(c1), "+r"(c2), "+r"(c3)
        : "r"(a[0]), "r"(a[1]), "r"(a[2]), "r"(a[3]), "r"(b0), "r"(b1));
}
__device__ __forceinline__ int q8(float v, float s) {
    int i = __float2int_rn(v * s);
    return i < -127 ? -127 : (i > 127 ? 127 : i);
}

// ---------------------------------------------------------------------------
// Prep 1: transpose dict[d][k] -> dictT[k][d] fp32 (refine/gather) + int8
// (screen B operand). Coalesced both sides.
// ---------------------------------------------------------------------------
__global__ void vq_transpose(const float* __restrict__ dict) {
    __shared__ float tile[32][33];
    const int kb = blockIdx.x * 32, db = blockIdx.y * 32;
    const int tx = threadIdx.x & 31, ty = threadIdx.x >> 5;
    #pragma unroll
    for (int r = ty; r < 32; r += 8)
        tile[r][tx] = dict[(size_t)(db + r) * K_CODES + kb + tx];
    __syncthreads();
    #pragma unroll
    for (int r = ty; r < 32; r += 8) {
        float v = tile[tx][r];
        g_dictT[(size_t)(kb + r) * D_DIM + db + tx] = v;
        g_dictQ[(size_t)(kb + r) * D_DIM + db + tx] = (int8_t)q8(v, DSCALE);
    }
}
// ---------------------------------------------------------------------------
// Prep 2: c_k = sum_d fl(d*d), SEQUENTIAL fp32 adds in d order (load-bearing).
// ---------------------------------------------------------------------------
__global__ void vq_norms(const float* __restrict__ dict) {
    int k = blockIdx.x * blockDim.x + threadIdx.x;
    if (k == 0) g_loss = 0.0;
    if (k < K_CODES) {
        float c = 0.f;
        for (int d = 0; d < D_DIM; ++d) {
            float v = dict[(size_t)d * K_CODES + k];
            c = __fadd_rn(c, __fmul_rn(v, v));
        }
        g_c[k] = c;
    }
}

// cp.async one dict code-tile (128 codes x 256 int8) into smem buffer.
__device__ __forceinline__ void load_b_tile(uint32_t sbase, int buf, int tt,
                                            int t) {
    const int8_t* src = g_dictQ + (size_t)tt * 128 * D_DIM;
    const uint32_t dstb = sbase + OFF_B + buf * (MTILE * BSTR);
    #pragma unroll
    for (int q = 0; q < 8; ++q) {
        int e   = t + THREADS * q;       // 2048 16B chunks
        int row = e >> 4;                // 16 chunks per 256B row
        int c16 = e & 15;
        cp16(dstb + (uint32_t)(row * BSTR + c16 * 16),
             src + (size_t)row * D_DIM + c16 * 16);
    }
}

#define TOP3_INS(cv, ci, v, code)                                              \
    do {                                                                       \
        if ((v) < (cv)[2]) {                                                   \
            if ((v) < (cv)[1]) {                                               \
                (cv)[2] = (cv)[1]; (ci)[2] = (ci)[1];                          \
                if ((v) < (cv)[0]) { (cv)[1] = (cv)[0]; (ci)[1] = (ci)[0];     \
                                     (cv)[0] = (v);     (ci)[0] = (code); }    \
                else               { (cv)[1] = (v);     (ci)[1] = (code); }    \
            } else                 { (cv)[2] = (v);     (ci)[2] = (code); }    \
        }                                                                      \
    } while (0)

// ---------------------------------------------------------------------------
// Main: IMMA screen -> 12 cand/row -> exact refine -> gather/loss.
// ---------------------------------------------------------------------------
__global__ __launch_bounds__(THREADS, 2)
void vq_main(const float* __restrict__ x, float* __restrict__ out) {
    extern __shared__ char smem[];
    float*          sC    = (float*)(smem + OFF_C);
    float*          sNf   = (float*)(smem + OFF_NF);
    unsigned short* sCand = (unsigned short*)(smem + OFF_CAND);
    unsigned long long* rowBest = (unsigned long long*)(smem + OFF_BEST);
    int*            sIdx  = (int*)(smem + OFF_IDX);

    const int t = threadIdx.x;
    const int w = t >> 5;
    const int l = t & 31;
    const size_t row0 = (size_t)blockIdx.x * MTILE;
    const uint32_t sbase = smem_u32(smem);

    // Stage c_k
    #pragma unroll
    for (int q = 0; q < 4; ++q) sC[t + THREADS * q] = g_c[t + THREADS * q];

    // Load x tile, quantize to int8 into sAq (screen operand only).
    #pragma unroll
    for (int q = 0; q < 8; ++q) {
        int e   = t + THREADS * q;       // 2048 16-elem chunks
        int r   = e >> 4;
        int d0  = (e & 15) * 16;
        const float4* xp = (const float4*)(x + (row0 + r) * D_DIM + d0);
        uint32_t pk[4];
        #pragma unroll
        for (int j = 0; j < 4; ++j) {
            float4 v = xp[j];
            uint32_t b0 = (uint32_t)(uint8_t)q8(v.x, XSCALE);
            uint32_t b1 = (uint32_t)(uint8_t)q8(v.y, XSCALE);
            uint32_t b2 = (uint32_t)(uint8_t)q8(v.z, XSCALE);
            uint32_t b3 = (uint32_t)(uint8_t)q8(v.w, XSCALE);
            pk[j] = b0 | (b1 << 8) | (b2 << 16) | (b3 << 24);
        }
        *(uint4*)(smem + OFF_AQ + (size_t)r * BSTR + d0) =
            make_uint4(pk[0], pk[1], pk[2], pk[3]);
    }

    // Start dict tiles 0 and 1
    load_b_tile(sbase, 0, 0, t); CP_COMMIT();
    load_b_tile(sbase, 1, 1, t); CP_COMMIT();

    // nf per row: EXACT sequential fp32 (load-bearing); init winners.
    if (t < MTILE) {
        float s = 0.f;
        const float* rowp = x + (row0 + t) * D_DIM;
        for (int d = 0; d < D_DIM; ++d)
            s = __fadd_rn(s, __fmul_rn(rowp[d], rowp[d]));
        sNf[t] = s;
        rowBest[t] = 0xFFFFFFFFFFFFFFFFull;
    }

    CP_WAIT(1);          // tile 0 landed
    __syncthreads();     // sAq + tile0 visible

    // A fragments for all K=256 (8 ksteps of 32 int8): afr[ks][0..3].
    // addr: row = w*16 + l%16, byte col = (l/16)*16 within the kstep.
    uint32_t afr[8][4];
    {
        uint32_t abase = sbase + OFF_AQ
            + (uint32_t)((w * 16 + (l & 15)) * BSTR + (l >> 4) * 16);
        #pragma unroll
        for (int ks = 0; ks < 8; ++ks)
            ldsm4(afr[ks][0], afr[ks][1], afr[ks][2], afr[ks][3],
                  abase + ks * 32);
    }

    // Per-lane top-3 for two rows: rA = w*16 + l/4, rB = rA + 8.
    float cvA[NCAND], cvB[NCAND];
    unsigned short ciA[NCAND], ciB[NCAND];
    #pragma unroll
    for (int q = 0; q < NCAND; ++q) {
        cvA[q] = __int_as_float(0x7f800000); ciA[q] = 0;
        cvB[q] = __int_as_float(0x7f800000); ciB[q] = 0;
    }

    for (int tt = 0; tt < NTILES; ++tt) {
        const uint32_t bbase = sbase + OFF_B + (tt & 1) * (MTILE * BSTR);
        #pragma unroll 2
        for (int n = 0; n < 16; ++n) {
            // B frags for 8 ksteps: 4x ldmatrix.x4.
            // addr: coderow = n*8 + l%8, byte col = (l/8)*16 (+ g*64).
            uint32_t bfr[8][2];
            const uint32_t bb = bbase
                + (uint32_t)((n * 8 + (l & 7)) * BSTR + (l >> 3) * 16);
            #pragma unroll
            for (int g = 0; g < 4; ++g)
                ldsm4(bfr[2 * g][0], bfr[2 * g][1],
                      bfr[2 * g + 1][0], bfr[2 * g + 1][1], bb + g * 64);

            // 2 independent accumulator sets (screen is order-free).
            int acc[2][4];
            #pragma unroll
            for (int s = 0; s < 2; ++s)
                #pragma unroll
                for (int e = 0; e < 4; ++e) acc[s][e] = 0;
            #pragma unroll
            for (int ks = 0; ks < 8; ++ks)
                imma16832(acc[ks & 1][0], acc[ks & 1][1],
                          acc[ks & 1][2], acc[ks & 1][3],
                          afr[ks], bfr[ks][0], bfr[ks][1]);
            int c0 = acc[0][0] + acc[1][0];
            int c1 = acc[0][1] + acc[1][1];
            int c2 = acc[0][2] + acc[1][2];
            int c3 = acc[0][3] + acc[1][3];

            // Fold: lane codes cb, cb+1; rows rA (c0,c1), rB (c2,c3).
            const int cb = tt * 128 + n * 8 + (l & 3) * 2;
            float ck0 = sC[cb], ck1 = sC[cb + 1];
            float vA0 = fmaf(-INV2, (float)c0, ck0);
            float vA1 = fmaf(-INV2, (float)c1, ck1);
            float vB0 = fmaf(-INV2, (float)c2, ck0);
            float vB1 = fmaf(-INV2, (float)c3, ck1);
            TOP3_INS(cvA, ciA, vA0, (unsigned short)cb);
            TOP3_INS(cvA, ciA, vA1, (unsigned short)(cb + 1));
            TOP3_INS(cvB, ciB, vB0, (unsigned short)cb);
            TOP3_INS(cvB, ciB, vB1, (unsigned short)(cb + 1));
        }
        __syncthreads();                     // done reading buf tt&1
        if (tt + 2 < NTILES) {
            load_b_tile(sbase, tt & 1, tt + 2, t); CP_COMMIT();
            CP_WAIT(1);                      // tile tt+1 landed
            __syncthreads();
        } else if (tt + 1 < NTILES) {
            CP_WAIT(0);                      // last tile landed
            __syncthreads();
        }
    }

    // Publish candidates: 4 lanes x top-3 = 12 per row.
    {
        int rA = w * 16 + (l >> 2);
        int rB = rA + 8;
        #pragma unroll
        for (int q = 0; q < NCAND; ++q) {
            sCand[rA * CPR + (l & 3) * NCAND + q] = ciA[q];
            sCand[rB * CPR + (l & 3) * NCAND + q] = ciB[q];
        }
    }
    __syncthreads();

    // Refine: thread t owns row t>>1, candidates (t&1)*6..+5. EXACT chains.
    {
        const int r = t >> 1;
        const float* xr = x + (row0 + r) * D_DIM;
        int   kk[6];
        float s6[6] = {0.f, 0.f, 0.f, 0.f, 0.f, 0.f};
        #pragma unroll
        for (int u = 0; u < 6; ++u)
            kk[u] = sCand[r * CPR + (t & 1) * 6 + u];
        for (int d = 0; d < D_DIM; d += 4) {
            float4 xv = *(const float4*)(xr + d);
            #pragma unroll
            for (int u = 0; u < 6; ++u) {
                float4 dv = *(const float4*)(g_dictT + (size_t)kk[u] * D_DIM + d);
                float s = s6[u];
                s = fmaf(xv.x, dv.x, s);
                s = fmaf(xv.y, dv.y, s);
                s = fmaf(xv.z, dv.z, s);
                s = fmaf(xv.w, dv.w, s);
                s6[u] = s;
            }
        }
        const float nf = sNf[r];
        #pragma unroll
        for (int u = 0; u < 6; ++u) {
            float t1 = __fadd_rn(nf, sC[kk[u]]);
            float v  = __fsub_rn(t1, __fmul_rn(2.f, s6[u]));
            unsigned long long pk =
                ((unsigned long long)__float_as_uint(v) << 32) | (unsigned)kk[u];
            atomicMin(&rowBest[r], pk);
        }
    }
    __syncthreads();
    if (t < MTILE) sIdx[t] = (int)(rowBest[t] & 0xFFFFFFFFull);
    __syncthreads();

    // Epilogue: q = 0.5*dictT[idx][d] (exact), write out, loss partial.
    float lsum = 0.f;
    for (int e = t; e < MTILE * D_DIM; e += THREADS) {
        int r = e >> 8, d = e & 255;
        int idx = sIdx[r];
        float q  = 0.5f * g_dictT[(size_t)idx * D_DIM + d];
        float xv = x[(row0 + r) * D_DIM + d];
        float df = xv - q;
        lsum = fmaf(df, df, lsum);
        out[(row0 + r) * D_DIM + d] = q;
    }
    #pragma unroll
    for (int o = 16; o > 0; o >>= 1)
        lsum += __shfl_xor_sync(0xffffffffu, lsum, o);
    float* sRed = (float*)sCand;     // candidates dead; reuse
    __syncthreads();
    if (l == 0) sRed[w] = lsum;
    __syncthreads();
    if (t == 0) {
        float s = 0.f;
        #pragma unroll
        for (int ww = 0; ww < THREADS / 32; ++ww) s += sRed[ww];
        atomicAdd(&g_loss, (double)s);
    }
}

// ---------------------------------------------------------------------------
// loss = 1.25 * mean((x - q)^2)
// ---------------------------------------------------------------------------
__global__ void vq_finalize(float* __restrict__ out, int loss_idx) {
    out[loss_idx] = (float)(1.25 * g_loss * (1.0 / (double)(N_ROWS * D_DIM)));
}

extern "C" void kernel_launch(void* const* d_in, const int* in_sizes, int n_in,
                              void* d_out, int out_size) {
    const float* x    = (const float*)d_in[0];
    const float* dict = (const float*)d_in[1];
    float* out = (float*)d_out;

    cudaFuncSetAttribute(vq_main, cudaFuncAttributeMaxDynamicSharedMemorySize,
                         SMEM_BYTES);

    vq_transpose<<<dim3(K_CODES / 32, D_DIM / 32), 256>>>(dict);
    vq_norms<<<16, 64>>>(dict);
    vq_main<<<N_ROWS / MTILE, THREADS, SMEM_BYTES>>>(x, out);
    vq_finalize<<<1, 1>>>(out, out_size - 1);
}